// round 1
// baseline (speedup 1.0000x reference)
#include <cuda_runtime.h>

#define NN 2048
#define DD 8
#define HH 64

// Scratch: __device__ globals (no allocation allowed in kernel_launch).
__device__ float g_sorted[HH * NN];        // per-h ascending-sorted X2 column
__device__ float g_suff[HH * (NN + 1)];    // per-h suffix sums of sorted column
__device__ float g_T[HH * NN];             // (S - D)[h][i]

// ---------------------------------------------------------------------------
// Kernel 1: one block per h. Compute X2[:,h] = messages @ W1[h, 8:16],
// bitonic-sort ascending in smem, suffix-sum (double accumulation), store.
// ---------------------------------------------------------------------------
__global__ void __launch_bounds__(1024) k_sort(const float* __restrict__ msg,
                                               const float* __restrict__ W1) {
    const int h = blockIdx.x;
    __shared__ float w[8];
    __shared__ float vals[NN];
    __shared__ double sd[NN];

    if (threadIdx.x < 8) w[threadIdx.x] = W1[h * 16 + 8 + threadIdx.x];
    __syncthreads();

    // X2 column for this h
    for (int j = threadIdx.x; j < NN; j += 1024) {
        const float4* m = reinterpret_cast<const float4*>(msg + j * 8);
        float4 m0 = m[0], m1 = m[1];
        vals[j] = m0.x * w[0] + m0.y * w[1] + m0.z * w[2] + m0.w * w[3]
                + m1.x * w[4] + m1.y * w[5] + m1.z * w[6] + m1.w * w[7];
    }

    // Bitonic sort, ascending
    for (int k = 2; k <= NN; k <<= 1) {
        for (int j = k >> 1; j > 0; j >>= 1) {
            __syncthreads();
            for (int t = threadIdx.x; t < NN; t += 1024) {
                int ixj = t ^ j;
                if (ixj > t) {
                    float a = vals[t], b = vals[ixj];
                    bool up = ((t & k) == 0);
                    if ((a > b) == up) { vals[t] = b; vals[ixj] = a; }
                }
            }
        }
    }
    __syncthreads();

    // Inclusive suffix scan (Hillis-Steele, reversed), double precision
    const int tA = threadIdx.x, tB = threadIdx.x + 1024;
    sd[tA] = (double)vals[tA];
    sd[tB] = (double)vals[tB];
    __syncthreads();
    for (int off = 1; off < NN; off <<= 1) {
        double r0 = (tA + off < NN) ? sd[tA + off] : 0.0;
        double r1 = (tB + off < NN) ? sd[tB + off] : 0.0;
        __syncthreads();
        sd[tA] += r0;
        sd[tB] += r1;
        __syncthreads();
    }

    g_sorted[h * NN + tA] = vals[tA];
    g_sorted[h * NN + tB] = vals[tB];
    g_suff[h * (NN + 1) + tA] = (float)sd[tA];
    g_suff[h * (NN + 1) + tB] = (float)sd[tB];
    if (threadIdx.x == 0) g_suff[h * (NN + 1) + NN] = 0.0f;
}

// ---------------------------------------------------------------------------
// Kernel 2: grid (4 i-chunks, 64 h). For each i:
//   a   = X1[i][h] + b1[h],  x2d = X2[i][h]
//   S   = a * |{x > -a}| + suffix_sum(first index with x > -a)   (exact relu-sum)
//   T[h][i] = S - relu(a + x2d)
// ---------------------------------------------------------------------------
__global__ void __launch_bounds__(256) k_search(const float* __restrict__ msg,
                                                const float* __restrict__ W1,
                                                const float* __restrict__ b1) {
    const int h = blockIdx.y;
    __shared__ float sv[NN];
    __shared__ float sf[NN + 1];
    __shared__ float wf[8], wb[8];
    __shared__ float b1h_s;

    for (int t = threadIdx.x; t < NN; t += 256) sv[t] = g_sorted[h * NN + t];
    for (int t = threadIdx.x; t < NN + 1; t += 256) sf[t] = g_suff[h * (NN + 1) + t];
    if (threadIdx.x < 8) wf[threadIdx.x] = W1[h * 16 + threadIdx.x];
    else if (threadIdx.x < 16) wb[threadIdx.x - 8] = W1[h * 16 + threadIdx.x];
    if (threadIdx.x == 0) b1h_s = b1[h];
    __syncthreads();

    const float b1h = b1h_s;
    const int ibase = blockIdx.x * (NN / 4);

    for (int i = ibase + threadIdx.x; i < ibase + NN / 4; i += 256) {
        const float4* m = reinterpret_cast<const float4*>(msg + i * 8);
        float4 m0 = m[0], m1 = m[1];
        float a = b1h
                + m0.x * wf[0] + m0.y * wf[1] + m0.z * wf[2] + m0.w * wf[3]
                + m1.x * wf[4] + m1.y * wf[5] + m1.z * wf[6] + m1.w * wf[7];
        float x2d = m0.x * wb[0] + m0.y * wb[1] + m0.z * wb[2] + m0.w * wb[3]
                  + m1.x * wb[4] + m1.y * wb[5] + m1.z * wb[6] + m1.w * wb[7];

        // lower bound of "strictly greater than -a" in ascending sv
        const float thr = -a;
        int lo = 0, hi = NN;
        while (lo < hi) {
            int mid = (lo + hi) >> 1;
            if (sv[mid] > thr) hi = mid; else lo = mid + 1;
        }
        float S = a * (float)(NN - lo) + sf[lo];
        float Dg = fmaxf(a + x2d, 0.0f);
        g_T[h * NN + i] = S - Dg;
    }
}

// ---------------------------------------------------------------------------
// Kernel 3: out[i][d] = (sum_h T[h][i] * W2[d][h]) / (N-1) + b2[d]
// ---------------------------------------------------------------------------
__global__ void __launch_bounds__(256) k_out(const float* __restrict__ W2,
                                             const float* __restrict__ b2,
                                             float* __restrict__ out) {
    __shared__ float w2s[DD * HH];
    __shared__ float b2s[DD];
    for (int t = threadIdx.x; t < DD * HH; t += 256) w2s[t] = W2[t];
    if (threadIdx.x < DD) b2s[threadIdx.x] = b2[threadIdx.x];
    __syncthreads();

    const int i = blockIdx.x * 256 + threadIdx.x;
    float acc[DD];
#pragma unroll
    for (int d = 0; d < DD; d++) acc[d] = 0.0f;

    for (int hh = 0; hh < HH; hh++) {
        float v = g_T[hh * NN + i];
#pragma unroll
        for (int d = 0; d < DD; d++) acc[d] += v * w2s[d * HH + hh];
    }
    const float inv = 1.0f / (float)(NN - 1);
#pragma unroll
    for (int d = 0; d < DD; d++) out[i * DD + d] = acc[d] * inv + b2s[d];
}

// ---------------------------------------------------------------------------
extern "C" void kernel_launch(void* const* d_in, const int* in_sizes, int n_in,
                              void* d_out, int out_size) {
    // Identify inputs by element count (all distinct): robust to ordering.
    const float* msg = nullptr;  // 2048*8   = 16384
    const float* W1  = nullptr;  // 64*16    = 1024
    const float* b1  = nullptr;  // 64
    const float* W2  = nullptr;  // 8*64     = 512
    const float* b2  = nullptr;  // 8
    for (int k = 0; k < n_in; k++) {
        switch (in_sizes[k]) {
            case 16384: msg = (const float*)d_in[k]; break;
            case 1024:  W1  = (const float*)d_in[k]; break;
            case 64:    b1  = (const float*)d_in[k]; break;
            case 512:   W2  = (const float*)d_in[k]; break;
            case 8:     b2  = (const float*)d_in[k]; break;
            default: break;
        }
    }
    float* out = (float*)d_out;

    k_sort<<<HH, 1024>>>(msg, W1);
    dim3 g2(4, HH);
    k_search<<<g2, 256>>>(msg, W1, b1);
    k_out<<<NN / 256, 256>>>(W2, b2, out);
}

// round 2
// speedup vs baseline: 1.4672x; 1.4672x over previous
#include <cuda_runtime.h>

#define NN 2048
#define DD 8
#define HH 64

// Scratch: __device__ globals (no allocation allowed in kernel_launch).
__device__ float g_sorted[HH * NN];        // per-h ascending-sorted X2 column
__device__ float g_suff[HH * (NN + 1)];    // per-h suffix sums of sorted column
__device__ float g_T[HH * NN];             // (S - D)[h][i]

// ---------------------------------------------------------------------------
// Kernel 1: one block (1024 thr) per h. Compute X2[:,h] = messages @ W1[h,8:16],
// bitonic-sort ascending (smem passes for j>=32, warp shuffles for j<=16),
// then a 2-barrier block suffix-scan in fp32.
// ---------------------------------------------------------------------------
__global__ void __launch_bounds__(1024) k_sort(const float* __restrict__ msg,
                                               const float* __restrict__ W1) {
    const int h = blockIdx.x;
    __shared__ float w[8];
    __shared__ float vals[NN];
    __shared__ float warpoff[32];
    __shared__ float sh_total;

    const int t = threadIdx.x;
    const int lane = t & 31;

    if (t < 8) w[t] = W1[h * 16 + 8 + t];
    __syncthreads();

    // X2 column for this h (indices t and t+1024)
    for (int j = t; j < NN; j += 1024) {
        const float4* m = reinterpret_cast<const float4*>(msg + j * 8);
        float4 m0 = m[0], m1 = m[1];
        vals[j] = m0.x * w[0] + m0.y * w[1] + m0.z * w[2] + m0.w * w[3]
                + m1.x * w[4] + m1.y * w[5] + m1.z * w[6] + m1.w * w[7];
    }
    __syncthreads();

    // Bitonic sort, ascending.
    for (int k = 2; k <= NN; k <<= 1) {
        // high phases (j >= 32): shared-memory compare-exchange
        for (int j = k >> 1; j >= 32; j >>= 1) {
            for (int base = t; base < NN; base += 1024) {
                int ixj = base ^ j;
                if (ixj > base) {
                    float a = vals[base], b = vals[ixj];
                    bool up = ((base & k) == 0);
                    if ((a > b) == up) { vals[base] = b; vals[ixj] = a; }
                }
            }
            __syncthreads();
        }
        // low phases (j <= 16): register + warp shuffle, single barrier at end
        {
            float v0 = vals[t];
            float v1 = vals[t + 1024];
            const bool up0 = ((t & k) == 0);
            const bool up1 = (((t + 1024) & k) == 0);
            const int jstart = ((k >> 1) < 32) ? (k >> 1) : 16;
#pragma unroll
            for (int j = 16; j >= 1; j >>= 1) {
                if (j <= jstart) {  // uniform condition per block
                    float p0 = __shfl_xor_sync(0xffffffffu, v0, j);
                    float p1 = __shfl_xor_sync(0xffffffffu, v1, j);
                    bool lower = ((t & j) == 0);
                    v0 = (lower == up0) ? fminf(v0, p0) : fmaxf(v0, p0);
                    v1 = (lower == up1) ? fminf(v1, p1) : fmaxf(v1, p1);
                }
            }
            vals[t] = v0;
            vals[t + 1024] = v1;
            __syncthreads();
        }
    }

    // Block scan (fp32): each thread owns pair (2t, 2t+1).
    float e0 = vals[2 * t], e1 = vals[2 * t + 1];
    float s = e0 + e1;
    // warp-inclusive scan of pair-sums
    float sc = s;
#pragma unroll
    for (int o = 1; o < 32; o <<= 1) {
        float n = __shfl_up_sync(0xffffffffu, sc, o);
        if (lane >= o) sc += n;
    }
    if (lane == 31) warpoff[t >> 5] = sc;
    __syncthreads();
    if (t < 32) {
        float ws = warpoff[t];
        float wsc = ws;
#pragma unroll
        for (int o = 1; o < 32; o <<= 1) {
            float n = __shfl_up_sync(0xffffffffu, wsc, o);
            if (t >= o) wsc += n;
        }
        warpoff[t] = wsc - ws;      // exclusive warp offset
        if (t == 31) sh_total = wsc;  // grand total
    }
    __syncthreads();

    const float total = sh_total;
    float excl = warpoff[t >> 5] + (sc - s);  // exclusive prefix before element 2t

    g_sorted[h * NN + 2 * t]     = e0;
    g_sorted[h * NN + 2 * t + 1] = e1;
    g_suff[h * (NN + 1) + 2 * t]     = total - excl;          // sum of vals[2t..]
    g_suff[h * (NN + 1) + 2 * t + 1] = total - (excl + e0);   // sum of vals[2t+1..]
    if (t == 0) g_suff[h * (NN + 1) + NN] = 0.0f;
}

// ---------------------------------------------------------------------------
// Kernel 2: grid (4 i-chunks, 64 h). For each i:
//   a   = X1[i][h] + b1[h],  x2d = X2[i][h]
//   S   = a * |{x > -a}| + suffix_sum(first index with x > -a)   (exact relu-sum)
//   T[h][i] = S - relu(a + x2d)
// ---------------------------------------------------------------------------
__global__ void __launch_bounds__(256) k_search(const float* __restrict__ msg,
                                                const float* __restrict__ W1,
                                                const float* __restrict__ b1) {
    const int h = blockIdx.y;
    __shared__ float sv[NN];
    __shared__ float sf[NN + 1];
    __shared__ float wf[8], wb[8];
    __shared__ float b1h_s;

    for (int t = threadIdx.x; t < NN; t += 256) sv[t] = g_sorted[h * NN + t];
    for (int t = threadIdx.x; t < NN + 1; t += 256) sf[t] = g_suff[h * (NN + 1) + t];
    if (threadIdx.x < 8) wf[threadIdx.x] = W1[h * 16 + threadIdx.x];
    else if (threadIdx.x < 16) wb[threadIdx.x - 8] = W1[h * 16 + threadIdx.x];
    if (threadIdx.x == 0) b1h_s = b1[h];
    __syncthreads();

    const float b1h = b1h_s;
    const int ibase = blockIdx.x * (NN / 4);

    for (int i = ibase + threadIdx.x; i < ibase + NN / 4; i += 256) {
        const float4* m = reinterpret_cast<const float4*>(msg + i * 8);
        float4 m0 = m[0], m1 = m[1];
        float a = b1h
                + m0.x * wf[0] + m0.y * wf[1] + m0.z * wf[2] + m0.w * wf[3]
                + m1.x * wf[4] + m1.y * wf[5] + m1.z * wf[6] + m1.w * wf[7];
        float x2d = m0.x * wb[0] + m0.y * wb[1] + m0.z * wb[2] + m0.w * wb[3]
                  + m1.x * wb[4] + m1.y * wb[5] + m1.z * wb[6] + m1.w * wb[7];

        // lower bound of "strictly greater than -a" in ascending sv
        const float thr = -a;
        int lo = 0, hi = NN;
        while (lo < hi) {
            int mid = (lo + hi) >> 1;
            if (sv[mid] > thr) hi = mid; else lo = mid + 1;
        }
        float S = a * (float)(NN - lo) + sf[lo];
        float Dg = fmaxf(a + x2d, 0.0f);
        g_T[h * NN + i] = S - Dg;
    }
}

// ---------------------------------------------------------------------------
// Kernel 3: out[i][d] = (sum_h T[h][i] * W2[d][h]) / (N-1) + b2[d]
// ---------------------------------------------------------------------------
__global__ void __launch_bounds__(256) k_out(const float* __restrict__ W2,
                                             const float* __restrict__ b2,
                                             float* __restrict__ out) {
    __shared__ float w2s[DD * HH];
    __shared__ float b2s[DD];
    for (int t = threadIdx.x; t < DD * HH; t += 256) w2s[t] = W2[t];
    if (threadIdx.x < DD) b2s[threadIdx.x] = b2[threadIdx.x];
    __syncthreads();

    const int i = blockIdx.x * 256 + threadIdx.x;
    float acc[DD];
#pragma unroll
    for (int d = 0; d < DD; d++) acc[d] = 0.0f;

    for (int hh = 0; hh < HH; hh++) {
        float v = g_T[hh * NN + i];
#pragma unroll
        for (int d = 0; d < DD; d++) acc[d] += v * w2s[d * HH + hh];
    }
    const float inv = 1.0f / (float)(NN - 1);
#pragma unroll
    for (int d = 0; d < DD; d++) out[i * DD + d] = acc[d] * inv + b2s[d];
}

// ---------------------------------------------------------------------------
extern "C" void kernel_launch(void* const* d_in, const int* in_sizes, int n_in,
                              void* d_out, int out_size) {
    // Identify inputs by element count (all distinct): robust to ordering.
    const float* msg = nullptr;  // 2048*8   = 16384
    const float* W1  = nullptr;  // 64*16    = 1024
    const float* b1  = nullptr;  // 64
    const float* W2  = nullptr;  // 8*64     = 512
    const float* b2  = nullptr;  // 8
    for (int k = 0; k < n_in; k++) {
        switch (in_sizes[k]) {
            case 16384: msg = (const float*)d_in[k]; break;
            case 1024:  W1  = (const float*)d_in[k]; break;
            case 64:    b1  = (const float*)d_in[k]; break;
            case 512:   W2  = (const float*)d_in[k]; break;
            case 8:     b2  = (const float*)d_in[k]; break;
            default: break;
        }
    }
    float* out = (float*)d_out;

    k_sort<<<HH, 1024>>>(msg, W1);
    dim3 g2(4, HH);
    k_search<<<g2, 256>>>(msg, W1, b1);
    k_out<<<NN / 256, 256>>>(W2, b2, out);
}

// round 3
// speedup vs baseline: 2.7173x; 1.8520x over previous
#include <cuda_runtime.h>

#define NN 2048
#define DD 8
#define HH 64
#define KB 2048          // histogram buckets
#define NTH 1024         // threads in k_main

// Scratch (no allocation allowed in kernel_launch).
__device__ float g_T[HH * NN];   // (S - D)[h][i]

// ---------------------------------------------------------------------------
// k_main: one block per h.
//   x1[j] = msg[j] @ W1[h,:8],  x2[j] = msg[j] @ W1[h,8:16]
//   Histogram x2 into KB bins over [lo,hi]; suffix-scan (cnt,sum);
//   F[b] = exact Sum_j relu(x_j - thr_b) at bin edges thr_b = lo + b*Delta.
//   Query per i: thr = -(x1_i + b1h); f via lerp of F (convex pw-linear,
//   exact at edges); T[h][i] = f - relu(a_i + x2_i).
// ---------------------------------------------------------------------------
__global__ void __launch_bounds__(NTH) k_main(const float* __restrict__ msg,
                                              const float* __restrict__ W1,
                                              const float* __restrict__ b1) {
    const int h = blockIdx.x;
    __shared__ float w[16];
    __shared__ float cnt[KB];
    __shared__ float sum[KB];
    __shared__ float Farr[KB + 1];
    __shared__ float redmin[32], redmax[32];
    __shared__ float wcC[32], wcS[32];
    __shared__ float sh_lo, sh_hi, sh_totC, sh_totS;

    const int t = threadIdx.x;
    const int lane = t & 31;
    const int wid = t >> 5;

    if (t < 16) w[t] = W1[h * 16 + t];
    const float b1h = __ldg(&b1[h]);
    // zero histogram (no barrier needed yet for w: used after barrier below)
    cnt[t] = 0.0f; cnt[t + NTH] = 0.0f;
    sum[t] = 0.0f; sum[t + NTH] = 0.0f;
    __syncthreads();  // (1) w ready, hist zeroed

    // two rows per thread
    const int j0 = t, j1 = t + NTH;
    const float4* m0p = reinterpret_cast<const float4*>(msg + j0 * 8);
    const float4* m1p = reinterpret_cast<const float4*>(msg + j1 * 8);
    float4 a0 = m0p[0], a1 = m0p[1];
    float4 c0 = m1p[0], c1 = m1p[1];

    float x1_0 = a0.x*w[0]+a0.y*w[1]+a0.z*w[2]+a0.w*w[3]
               + a1.x*w[4]+a1.y*w[5]+a1.z*w[6]+a1.w*w[7];
    float x2_0 = a0.x*w[8]+a0.y*w[9]+a0.z*w[10]+a0.w*w[11]
               + a1.x*w[12]+a1.y*w[13]+a1.z*w[14]+a1.w*w[15];
    float x1_1 = c0.x*w[0]+c0.y*w[1]+c0.z*w[2]+c0.w*w[3]
               + c1.x*w[4]+c1.y*w[5]+c1.z*w[6]+c1.w*w[7];
    float x2_1 = c0.x*w[8]+c0.y*w[9]+c0.z*w[10]+c0.w*w[11]
               + c1.x*w[12]+c1.y*w[13]+c1.z*w[14]+c1.w*w[15];

    // block min/max of x2
    float mn = fminf(x2_0, x2_1), mx = fmaxf(x2_0, x2_1);
#pragma unroll
    for (int o = 16; o >= 1; o >>= 1) {
        mn = fminf(mn, __shfl_xor_sync(0xffffffffu, mn, o));
        mx = fmaxf(mx, __shfl_xor_sync(0xffffffffu, mx, o));
    }
    if (lane == 0) { redmin[wid] = mn; redmax[wid] = mx; }
    __syncthreads();  // (2)
    if (t < 32) {
        float m2 = redmin[t], x2m = redmax[t];
#pragma unroll
        for (int o = 16; o >= 1; o >>= 1) {
            m2 = fminf(m2, __shfl_xor_sync(0xffffffffu, m2, o));
            x2m = fmaxf(x2m, __shfl_xor_sync(0xffffffffu, x2m, o));
        }
        if (t == 0) {
            sh_lo = m2;
            sh_hi = x2m;
        }
    }
    __syncthreads();  // (3)

    const float lo = sh_lo, hi = sh_hi;
    const float range = fmaxf(hi - lo, 1e-30f);
    const float invD = (float)KB / range;
    const float Delta = range / (float)KB;

    // histogram (smem float atomics; spread addresses)
    int bi0 = (int)((x2_0 - lo) * invD); bi0 = bi0 > KB - 1 ? KB - 1 : (bi0 < 0 ? 0 : bi0);
    int bi1 = (int)((x2_1 - lo) * invD); bi1 = bi1 > KB - 1 ? KB - 1 : (bi1 < 0 ? 0 : bi1);
    atomicAdd(&cnt[bi0], 1.0f); atomicAdd(&sum[bi0], x2_0);
    atomicAdd(&cnt[bi1], 1.0f); atomicAdd(&sum[bi1], x2_1);
    __syncthreads();  // (4)

    // block prefix scan over bucket pairs (channels: cnt, sum)
    float pc0 = cnt[2 * t], pc1 = cnt[2 * t + 1];
    float ps0 = sum[2 * t], ps1 = sum[2 * t + 1];
    float csum = pc0 + pc1, ssum = ps0 + ps1;
    float cI = csum, sI = ssum;
#pragma unroll
    for (int o = 1; o < 32; o <<= 1) {
        float nc = __shfl_up_sync(0xffffffffu, cI, o);
        float ns = __shfl_up_sync(0xffffffffu, sI, o);
        if (lane >= o) { cI += nc; sI += ns; }
    }
    if (lane == 31) { wcC[wid] = cI; wcS[wid] = sI; }
    __syncthreads();  // (5)
    if (t < 32) {
        float oc = wcC[t], os = wcS[t];
        float ocI = oc, osI = os;
#pragma unroll
        for (int o = 1; o < 32; o <<= 1) {
            float nc = __shfl_up_sync(0xffffffffu, ocI, o);
            float ns = __shfl_up_sync(0xffffffffu, osI, o);
            if (t >= o) { ocI += nc; osI += ns; }
        }
        wcC[t] = ocI - oc;  // exclusive warp offsets
        wcS[t] = osI - os;
        if (t == 31) { sh_totC = ocI; sh_totS = osI; }
    }
    __syncthreads();  // (6)

    const float totC = sh_totC, totS = sh_totS;
    float exC = wcC[wid] + (cI - csum);   // exclusive prefix before bucket 2t
    float exS = wcS[wid] + (sI - ssum);

    // F[b] = sumAbove[b] - thr_b * cntAbove[b]   (exact at edges)
    {
        float cAb0 = totC - exC;
        float sAb0 = totS - exS;
        float cAb1 = cAb0 - pc0;
        float sAb1 = sAb0 - ps0;
        float thr0 = lo + (float)(2 * t) * Delta;
        float thr1 = lo + (float)(2 * t + 1) * Delta;
        Farr[2 * t]     = sAb0 - thr0 * cAb0;
        Farr[2 * t + 1] = sAb1 - thr1 * cAb1;
        if (t == 0) Farr[KB] = 0.0f;
    }
    __syncthreads();  // (7)

    // queries
#pragma unroll
    for (int r = 0; r < 2; r++) {
        float x1v = r ? x1_1 : x1_0;
        float x2v = r ? x2_1 : x2_0;
        int j = r ? j1 : j0;
        float a = x1v + b1h;
        float thr = -a;
        float f;
        if (thr < lo) {
            f = totS - thr * (float)NN;           // exact: all elements active
        } else if (thr >= hi) {
            f = 0.0f;                              // exact: none active
        } else {
            float u = (thr - lo) * invD;
            int b = (int)u; b = b > KB - 1 ? KB - 1 : b;
            float frac = u - (float)b;
            float f0 = Farr[b], f1 = Farr[b + 1];
            f = f0 + frac * (f1 - f0);
        }
        float Dg = fmaxf(a + x2v, 0.0f);
        g_T[h * NN + j] = f - Dg;
    }
}

// ---------------------------------------------------------------------------
// k_out: out[i][d] = (sum_h T[h][i] * W2[d][h]) / (N-1) + b2[d]
// ---------------------------------------------------------------------------
__global__ void __launch_bounds__(128) k_out(const float* __restrict__ W2,
                                             const float* __restrict__ b2,
                                             float* __restrict__ out) {
    __shared__ float w2s[DD * HH];
    __shared__ float b2s[DD];
    for (int t = threadIdx.x; t < DD * HH; t += 128) w2s[t] = W2[t];
    if (threadIdx.x < DD) b2s[threadIdx.x] = b2[threadIdx.x];
    __syncthreads();

    const int i = blockIdx.x * 128 + threadIdx.x;
    float acc[DD];
#pragma unroll
    for (int d = 0; d < DD; d++) acc[d] = 0.0f;

#pragma unroll 8
    for (int hh = 0; hh < HH; hh++) {
        float v = g_T[hh * NN + i];
#pragma unroll
        for (int d = 0; d < DD; d++) acc[d] += v * w2s[d * HH + hh];
    }
    const float inv = 1.0f / (float)(NN - 1);
#pragma unroll
    for (int d = 0; d < DD; d++) out[i * DD + d] = acc[d] * inv + b2s[d];
}

// ---------------------------------------------------------------------------
extern "C" void kernel_launch(void* const* d_in, const int* in_sizes, int n_in,
                              void* d_out, int out_size) {
    // Identify inputs by element count (all distinct): robust to ordering.
    const float* msg = nullptr;  // 2048*8   = 16384
    const float* W1  = nullptr;  // 64*16    = 1024
    const float* b1  = nullptr;  // 64
    const float* W2  = nullptr;  // 8*64     = 512
    const float* b2  = nullptr;  // 8
    for (int k = 0; k < n_in; k++) {
        switch (in_sizes[k]) {
            case 16384: msg = (const float*)d_in[k]; break;
            case 1024:  W1  = (const float*)d_in[k]; break;
            case 64:    b1  = (const float*)d_in[k]; break;
            case 512:   W2  = (const float*)d_in[k]; break;
            case 8:     b2  = (const float*)d_in[k]; break;
            default: break;
        }
    }
    float* out = (float*)d_out;

    k_main<<<HH, NTH>>>(msg, W1, b1);
    k_out<<<NN / 128, 128>>>(W2, b2, out);
}

// round 4
// speedup vs baseline: 4.2746x; 1.5731x over previous
#include <cuda_runtime.h>

#define NN 2048
#define DD 8
#define HH 64
#define KB 2048          // histogram buckets
#define NTH 1024         // threads in k_main

// Scratch (no allocation allowed in kernel_launch).
__device__ float g_T[HH * NN];   // (S - D)[h][i]

// ---------------------------------------------------------------------------
// k_main: one block per h.
//   x1[j] = msg[j] @ W1[h,:8],  x2[j] = msg[j] @ W1[h,8:16]
//   Histogram x2 into KB bins over [lo,hi]; suffix-scan (cnt,sum);
//   F[b] = exact Sum_j relu(x_j - thr_b) at bin edges thr_b = lo + b*Delta.
//   Query per i: thr = -(x1_i + b1h); f via lerp of F (convex pw-linear,
//   exact at edges); T[h][i] = f - relu(a_i + x2_i).
// ---------------------------------------------------------------------------
__global__ void __launch_bounds__(NTH) k_main(const float* __restrict__ msg,
                                              const float* __restrict__ W1,
                                              const float* __restrict__ b1) {
    const int h = blockIdx.x;
    __shared__ float w[16];
    __shared__ float cnt[KB];
    __shared__ float sum[KB];
    __shared__ float Farr[KB + 1];
    __shared__ float redmin[32], redmax[32];
    __shared__ float wcC[32], wcS[32];
    __shared__ float sh_lo, sh_hi, sh_totC, sh_totS;

    const int t = threadIdx.x;
    const int lane = t & 31;
    const int wid = t >> 5;

    if (t < 16) w[t] = W1[h * 16 + t];
    const float b1h = __ldg(&b1[h]);
    // zero histogram
    cnt[t] = 0.0f; cnt[t + NTH] = 0.0f;
    sum[t] = 0.0f; sum[t + NTH] = 0.0f;
    __syncthreads();  // (1) w ready, hist zeroed

    // two rows per thread
    const int j0 = t, j1 = t + NTH;
    const float4* m0p = reinterpret_cast<const float4*>(msg + j0 * 8);
    const float4* m1p = reinterpret_cast<const float4*>(msg + j1 * 8);
    float4 a0 = m0p[0], a1 = m0p[1];
    float4 c0 = m1p[0], c1 = m1p[1];

    float x1_0 = a0.x*w[0]+a0.y*w[1]+a0.z*w[2]+a0.w*w[3]
               + a1.x*w[4]+a1.y*w[5]+a1.z*w[6]+a1.w*w[7];
    float x2_0 = a0.x*w[8]+a0.y*w[9]+a0.z*w[10]+a0.w*w[11]
               + a1.x*w[12]+a1.y*w[13]+a1.z*w[14]+a1.w*w[15];
    float x1_1 = c0.x*w[0]+c0.y*w[1]+c0.z*w[2]+c0.w*w[3]
               + c1.x*w[4]+c1.y*w[5]+c1.z*w[6]+c1.w*w[7];
    float x2_1 = c0.x*w[8]+c0.y*w[9]+c0.z*w[10]+c0.w*w[11]
               + c1.x*w[12]+c1.y*w[13]+c1.z*w[14]+c1.w*w[15];

    // block min/max of x2
    float mn = fminf(x2_0, x2_1), mx = fmaxf(x2_0, x2_1);
#pragma unroll
    for (int o = 16; o >= 1; o >>= 1) {
        mn = fminf(mn, __shfl_xor_sync(0xffffffffu, mn, o));
        mx = fmaxf(mx, __shfl_xor_sync(0xffffffffu, mx, o));
    }
    if (lane == 0) { redmin[wid] = mn; redmax[wid] = mx; }
    __syncthreads();  // (2)
    if (t < 32) {
        float m2 = redmin[t], x2m = redmax[t];
#pragma unroll
        for (int o = 16; o >= 1; o >>= 1) {
            m2 = fminf(m2, __shfl_xor_sync(0xffffffffu, m2, o));
            x2m = fmaxf(x2m, __shfl_xor_sync(0xffffffffu, x2m, o));
        }
        if (t == 0) {
            sh_lo = m2;
            sh_hi = x2m;
        }
    }
    __syncthreads();  // (3)

    const float lo = sh_lo, hi = sh_hi;
    const float range = fmaxf(hi - lo, 1e-30f);
    const float invD = (float)KB / range;
    const float Delta = range / (float)KB;

    // histogram (smem float atomics; spread addresses)
    int bi0 = (int)((x2_0 - lo) * invD); bi0 = bi0 > KB - 1 ? KB - 1 : (bi0 < 0 ? 0 : bi0);
    int bi1 = (int)((x2_1 - lo) * invD); bi1 = bi1 > KB - 1 ? KB - 1 : (bi1 < 0 ? 0 : bi1);
    atomicAdd(&cnt[bi0], 1.0f); atomicAdd(&sum[bi0], x2_0);
    atomicAdd(&cnt[bi1], 1.0f); atomicAdd(&sum[bi1], x2_1);
    __syncthreads();  // (4)

    // block prefix scan over bucket pairs (channels: cnt, sum)
    float pc0 = cnt[2 * t], pc1 = cnt[2 * t + 1];
    float ps0 = sum[2 * t], ps1 = sum[2 * t + 1];
    float csum = pc0 + pc1, ssum = ps0 + ps1;
    float cI = csum, sI = ssum;
#pragma unroll
    for (int o = 1; o < 32; o <<= 1) {
        float nc = __shfl_up_sync(0xffffffffu, cI, o);
        float ns = __shfl_up_sync(0xffffffffu, sI, o);
        if (lane >= o) { cI += nc; sI += ns; }
    }
    if (lane == 31) { wcC[wid] = cI; wcS[wid] = sI; }
    __syncthreads();  // (5)
    if (t < 32) {
        float oc = wcC[t], os = wcS[t];
        float ocI = oc, osI = os;
#pragma unroll
        for (int o = 1; o < 32; o <<= 1) {
            float nc = __shfl_up_sync(0xffffffffu, ocI, o);
            float ns = __shfl_up_sync(0xffffffffu, osI, o);
            if (t >= o) { ocI += nc; osI += ns; }
        }
        wcC[t] = ocI - oc;  // exclusive warp offsets
        wcS[t] = osI - os;
        if (t == 31) { sh_totC = ocI; sh_totS = osI; }
    }
    __syncthreads();  // (6)

    const float totC = sh_totC, totS = sh_totS;
    float exC = wcC[wid] + (cI - csum);   // exclusive prefix before bucket 2t
    float exS = wcS[wid] + (sI - ssum);

    // F[b] = sumAbove[b] - thr_b * cntAbove[b]   (exact at edges)
    {
        float cAb0 = totC - exC;
        float sAb0 = totS - exS;
        float cAb1 = cAb0 - pc0;
        float sAb1 = sAb0 - ps0;
        float thr0 = lo + (float)(2 * t) * Delta;
        float thr1 = lo + (float)(2 * t + 1) * Delta;
        Farr[2 * t]     = sAb0 - thr0 * cAb0;
        Farr[2 * t + 1] = sAb1 - thr1 * cAb1;
        if (t == 0) Farr[KB] = 0.0f;
    }
    __syncthreads();  // (7)

    // queries
#pragma unroll
    for (int r = 0; r < 2; r++) {
        float x1v = r ? x1_1 : x1_0;
        float x2v = r ? x2_1 : x2_0;
        int j = r ? j1 : j0;
        float a = x1v + b1h;
        float thr = -a;
        float f;
        if (thr < lo) {
            f = totS - thr * (float)NN;           // exact: all elements active
        } else if (thr >= hi) {
            f = 0.0f;                              // exact: none active
        } else {
            float u = (thr - lo) * invD;
            int b = (int)u; b = b > KB - 1 ? KB - 1 : b;
            float frac = u - (float)b;
            float f0 = Farr[b], f1 = Farr[b + 1];
            f = f0 + frac * (f1 - f0);
        }
        float Dg = fmaxf(a + x2v, 0.0f);
        g_T[h * NN + j] = f - Dg;
    }
}

// ---------------------------------------------------------------------------
// k_out: out[i][d] = (sum_h T[h][i] * W2[d][h]) / (N-1) + b2[d]
// 64 blocks x 256 thr. Block owns 32 i's; warp w owns h in [8w, 8w+8) for
// those 32 i's (coalesced 128B row segments, MLP=8). Cross-warp reduce in smem.
// ---------------------------------------------------------------------------
__global__ void __launch_bounds__(256) k_out(const float* __restrict__ W2,
                                             const float* __restrict__ b2,
                                             float* __restrict__ out) {
    __shared__ float w2s[DD * HH];
    __shared__ float b2s[DD];
    __shared__ float red[8][32][DD];   // 8 KB partials

    const int t = threadIdx.x;
    const int lane = t & 31;
    const int wid = t >> 5;

    for (int k = t; k < DD * HH; k += 256) w2s[k] = W2[k];
    if (t < DD) b2s[t] = b2[t];
    __syncthreads();

    const int i = blockIdx.x * 32 + lane;
    float acc[DD];
#pragma unroll
    for (int d = 0; d < DD; d++) acc[d] = 0.0f;

#pragma unroll
    for (int k = 0; k < 8; k++) {
        const int hh = wid * 8 + k;
        float v = g_T[hh * NN + i];
#pragma unroll
        for (int d = 0; d < DD; d++) acc[d] += v * w2s[d * HH + hh];
    }
#pragma unroll
    for (int d = 0; d < DD; d++) red[wid][lane][d] = acc[d];
    __syncthreads();

    // thread t -> (i_local = t>>3, d = t&7); read red[*][il][d] (coalesced)
    const int il = t >> 3, d = t & 7;
    float s = 0.0f;
#pragma unroll
    for (int wdx = 0; wdx < 8; wdx++) s += red[wdx][il][d];
    out[blockIdx.x * 256 + t] = s * (1.0f / (float)(NN - 1)) + b2s[d];
}

// ---------------------------------------------------------------------------
extern "C" void kernel_launch(void* const* d_in, const int* in_sizes, int n_in,
                              void* d_out, int out_size) {
    // Identify inputs by element count (all distinct): robust to ordering.
    const float* msg = nullptr;  // 2048*8   = 16384
    const float* W1  = nullptr;  // 64*16    = 1024
    const float* b1  = nullptr;  // 64
    const float* W2  = nullptr;  // 8*64     = 512
    const float* b2  = nullptr;  // 8
    for (int k = 0; k < n_in; k++) {
        switch (in_sizes[k]) {
            case 16384: msg = (const float*)d_in[k]; break;
            case 1024:  W1  = (const float*)d_in[k]; break;
            case 64:    b1  = (const float*)d_in[k]; break;
            case 512:   W2  = (const float*)d_in[k]; break;
            case 8:     b2  = (const float*)d_in[k]; break;
            default: break;
        }
    }
    float* out = (float*)d_out;

    k_main<<<HH, NTH>>>(msg, W1, b1);
    k_out<<<NN / 32, 256>>>(W2, b2, out);
}